// round 8
// baseline (speedup 1.0000x reference)
#include <cuda_runtime.h>
#include <cuda_fp8.h>
#include <cfloat>
#include <cstdint>

#define N_Q    2048
#define M_B    100000
#define M_PAD  100224
#define KNN    5
#define SPLITS 37
#define RPS    2703            /* 37*2703 = 100011 >= 100000 */
#define BT     128
#define NT     22              /* ceil(2703/128); max staged row 100124 < M_PAD */
#define QTILES 16
#define NCAND  (SPLITS * KNN)  /* 185 */
#define NREF   24              /* exact-refined candidates per query */

// ---------------------------------------------------------------------------
// device scratch: fp8 rows (128 B), scales, coarse candidates (idx packed)
// ---------------------------------------------------------------------------
__device__ __align__(256) uint32_t g_bankq[(size_t)M_PAD * 32];
__device__ __align__(256) uint32_t g_featq[(size_t)N_Q * 32];
__device__ float g_y2p[M_PAD];     // exact ||y||^2 (INF for padding)
__device__ float g_ysp[M_PAD];     // 2 * bank row scale (0 for padding)
__device__ float g_sxp[N_Q];       // query row scale
__device__ float g_scr[(size_t)N_Q * NCAND];   // packed (dist | 12-bit local idx)

#define SWZ(o) ((o) ^ (((o) >> 3) & 0x70))

__device__ __forceinline__ uint32_t smem_u32(const void* p) {
    uint32_t a;
    asm("{ .reg .u64 t; cvta.to.shared.u64 t, %1; cvt.u32.u64 %0, t; }" : "=r"(a) : "l"(p));
    return a;
}

#define CP16(dst, src) asm volatile("cp.async.cg.shared.global [%0], [%1], 16;" :: "r"(dst), "l"(src))
#define CP_COMMIT()    asm volatile("cp.async.commit_group;" ::: "memory")
#define CP_WAIT1()     asm volatile("cp.async.wait_group 1;" ::: "memory")
#define CP_WAIT0()     asm volatile("cp.async.wait_group 0;" ::: "memory")

#define LDSM4(r0, r1, r2, r3, a)                                               \
    asm volatile("ldmatrix.sync.aligned.m8n8.x4.shared.b16 {%0,%1,%2,%3}, [%4];" \
        : "=r"(r0), "=r"(r1), "=r"(r2), "=r"(r3) : "r"(a))

__device__ __forceinline__ void mma16832e4(float* c,
    uint32_t a0, uint32_t a1, uint32_t a2, uint32_t a3, uint32_t b0, uint32_t b1) {
    asm("mma.sync.aligned.m16n8k32.row.col.f32.e4m3.e4m3.f32 "
        "{%0,%1,%2,%3}, {%4,%5,%6,%7}, {%8,%9}, {%0,%1,%2,%3};"
        : "+f"(c[0]), "+f"(c[1]), "+f"(c[2]), "+f"(c[3])
        : "r"(a0), "r"(a1), "r"(a2), "r"(a3), "r"(b0), "r"(b1));
}

__device__ __forceinline__ void insert5(float* t, float d) {
    t[4] = d;
#pragma unroll
    for (int s = 4; s > 0; --s) {
        float lo = fminf(t[s], t[s - 1]);
        float hi = fmaxf(t[s], t[s - 1]);
        t[s - 1] = lo; t[s] = hi;
    }
}

__device__ __forceinline__ uint32_t quant4fp8(float4 v, float sc) {
    __nv_fp8_storage_t b0 = __nv_cvt_float_to_fp8(v.x * sc, __NV_SATFINITE, __NV_E4M3);
    __nv_fp8_storage_t b1 = __nv_cvt_float_to_fp8(v.y * sc, __NV_SATFINITE, __NV_E4M3);
    __nv_fp8_storage_t b2 = __nv_cvt_float_to_fp8(v.z * sc, __NV_SATFINITE, __NV_E4M3);
    __nv_fp8_storage_t b3 = __nv_cvt_float_to_fp8(v.w * sc, __NV_SATFINITE, __NV_E4M3);
    return (uint32_t)b0 | ((uint32_t)b1 << 8) | ((uint32_t)b2 << 16) | ((uint32_t)b3 << 24);
}

// ---------------------------------------------------------------------------
// prep: per-row absmax fp8 quantization; bank also exact y2 + 2*scale
// ---------------------------------------------------------------------------
__global__ void prep_bank(const float* __restrict__ bank) {
    int r = (blockIdx.x * blockDim.x + threadIdx.x) >> 5;
    int lane = threadIdx.x & 31;
    if (r >= M_PAD) return;
    float4 v = make_float4(0.f, 0.f, 0.f, 0.f);
    if (r < M_B) v = *reinterpret_cast<const float4*>(bank + (size_t)r * 128 + lane * 4);
    float mx = fmaxf(fmaxf(fabsf(v.x), fabsf(v.y)), fmaxf(fabsf(v.z), fabsf(v.w)));
    float s2 = v.x * v.x + v.y * v.y + v.z * v.z + v.w * v.w;
#pragma unroll
    for (int o = 16; o; o >>= 1) {
        mx = fmaxf(mx, __shfl_xor_sync(0xFFFFFFFFu, mx, o));
        s2 += __shfl_xor_sync(0xFFFFFFFFu, s2, o);
    }
    float sc = (mx > 0.f) ? (448.f / mx) : 0.f;
    g_bankq[(size_t)r * 32 + lane] = quant4fp8(v, sc);
    if (lane == 0) {
        g_y2p[r] = (r < M_B) ? s2 : __int_as_float(0x7f800000);
        g_ysp[r] = 2.f * mx * (1.f / 448.f);
    }
}

__global__ void prep_feat(const float* __restrict__ feat) {
    int r = (blockIdx.x * blockDim.x + threadIdx.x) >> 5;
    int lane = threadIdx.x & 31;
    if (r >= N_Q) return;
    float4 v = *reinterpret_cast<const float4*>(feat + (size_t)r * 128 + lane * 4);
    float mx = fmaxf(fmaxf(fabsf(v.x), fabsf(v.y)), fmaxf(fabsf(v.z), fabsf(v.w)));
#pragma unroll
    for (int o = 16; o; o >>= 1) mx = fmaxf(mx, __shfl_xor_sync(0xFFFFFFFFu, mx, o));
    float sc = (mx > 0.f) ? (448.f / mx) : 0.f;
    g_featq[(size_t)r * 32 + lane] = quant4fp8(v, sc);
    if (lane == 0) g_sxp[r] = mx * (1.f / 448.f);
}

// ---------------------------------------------------------------------------
// main: 128q x 128m x K128 fp8 QMMA + fused coarse top-5 (idx packed low 12b)
// smem: A 16KB @0 | B 2x16KB @16384 | y2 2x512 @49152 | ys 2x512 @50176 |
//       sx 512 @51200. merge buffer reuses base.
// ---------------------------------------------------------------------------
#define SMEM_SZ 51712

__global__ void __launch_bounds__(256, 2)
knn_main() {
    extern __shared__ __align__(1024) char smem[];
    const uint32_t sb = smem_u32(smem);
    const int tid  = threadIdx.x;
    const int wid  = tid >> 5;
    const int lane = tid & 31;
    const int wq = (wid >> 1) * 32;     // 0,32,64,96
    const int wm = (wid & 1) * 64;      // 0,64

    const int split  = blockIdx.x;
    const int q0     = blockIdx.y * 128;
    const int rbegin = split * RPS;
    const int rend   = min(rbegin + RPS, M_B);

    // ---- A tile: 128 rows x 128B fp8, swizzled, loaded once; sx staged ----
    {
        const char* ga = (const char*)g_featq + (size_t)q0 * 128;
#pragma unroll
        for (int it = 0; it < 4; ++it) {
            int seg = it * 256 + tid;
            int row = seg >> 3, by = (seg & 7) << 4;
            float4 v = *reinterpret_cast<const float4*>(ga + row * 128 + by);
            *reinterpret_cast<float4*>(smem + SWZ(row * 128 + by)) = v;
        }
        if (tid < 128) ((float*)(smem + 51200))[tid] = g_sxp[q0 + tid];
    }

    // ---- lane-invariant fragment addresses ----
    const int ka = (lane & 16) ? 16 : 0;
    uint32_t aBase[2]; int xa[2];
#pragma unroll
    for (int mt = 0; mt < 2; ++mt) {
        int mrow = wq + mt * 16 + (lane & 15);
        aBase[mt] = sb + mrow * 128;
        xa[mt] = (mrow & 7) * 16;
    }
    const int kb = ((lane >> 4) & 1) * 16;
    const int nr = ((lane >> 3) & 1) * 8 + (lane & 7);
    uint32_t bRel[4]; int xb[4];
#pragma unroll
    for (int g = 0; g < 4; ++g) {
        int nrow = wm + g * 16 + nr;
        bRel[g] = nrow * 128;
        xb[g] = (nrow & 7) * 16;
    }

    // ---- B stage (y2/ys via plain LDG/STS: r0 only 4B-aligned) ----
    auto stageB = [&](int st, int r0) {
        const char* gb = (const char*)g_bankq + (size_t)r0 * 128;
        uint32_t bs = sb + 16384 + st * 16384;
#pragma unroll
        for (int it = 0; it < 4; ++it) {
            int seg = it * 256 + tid;
            int row = seg >> 3, by = (seg & 7) << 4;
            CP16(bs + SWZ(row * 128 + by), gb + row * 128 + by);
        }
        CP_COMMIT();
        if (tid < BT) {
            ((float*)(smem + 49152 + st * 512))[tid] = g_y2p[r0 + tid];
            ((float*)(smem + 50176 + st * 512))[tid] = g_ysp[r0 + tid];
        }
    };

    stageB(0, rbegin);

    float topv[4][KNN];
#pragma unroll
    for (int i = 0; i < 4; ++i)
#pragma unroll
        for (int s = 0; s < KNN; ++s) topv[i][s] = FLT_MAX;

    const float INF = __int_as_float(0x7f800000);
    __syncthreads();   // sx staged

    float nsx[4];
#pragma unroll
    for (int mt = 0; mt < 2; ++mt)
#pragma unroll
        for (int half = 0; half < 2; ++half)
            nsx[mt * 2 + half] = -((const float*)(smem + 51200))[wq + mt * 16 + half * 8 + (lane >> 2)];

    for (int t = 0; t < NT; ++t) {
        const int st = t & 1;
        const int r0 = rbegin + t * BT;
        if (t + 1 < NT) { stageB(st ^ 1, r0 + BT); CP_WAIT1(); }
        else            { CP_WAIT0(); }
        __syncthreads();

        float acc[2][8][4];
#pragma unroll
        for (int mt = 0; mt < 2; ++mt)
#pragma unroll
            for (int nt = 0; nt < 8; ++nt)
#pragma unroll
                for (int c = 0; c < 4; ++c) acc[mt][nt][c] = 0.f;

        const uint32_t bs = sb + 16384 + st * 16384;
#pragma unroll
        for (int ks = 0; ks < 4; ++ks) {
            const int kk = ks * 32;
            uint32_t A[2][4], B[4][4];
            LDSM4(A[0][0], A[0][1], A[0][2], A[0][3], aBase[0] + ((kk + ka) ^ xa[0]));
            LDSM4(A[1][0], A[1][1], A[1][2], A[1][3], aBase[1] + ((kk + ka) ^ xa[1]));
#pragma unroll
            for (int g = 0; g < 4; ++g)
                LDSM4(B[g][0], B[g][1], B[g][2], B[g][3],
                      bs + bRel[g] + ((kk + kb) ^ xb[g]));
#pragma unroll
            for (int mt = 0; mt < 2; ++mt)
#pragma unroll
                for (int nt = 0; nt < 8; ++nt)
                    mma16832e4(acc[mt][nt], A[mt][0], A[mt][1], A[mt][2], A[mt][3],
                               B[nt >> 1][nt & 1], B[nt >> 1][(nt & 1) + 2]);
        }

        // ---- fused coarse epilogue: d = y2 - sx*ys*acc, idx packed low 12b ----
        const float* y2s = (const float*)(smem + 49152 + st * 512);
        const float* yss = (const float*)(smem + 50176 + st * 512);
        const int lim = rend - r0;
#pragma unroll
        for (int nt = 0; nt < 8; ++nt) {
#pragma unroll
            for (int j = 0; j < 2; ++j) {
                int col = wm + nt * 8 + (lane & 3) * 2 + j;
                bool ok = col < lim;
                float y2c = ok ? y2s[col] : INF;
                float ysc = ok ? yss[col] : 0.f;
                uint32_t loc = (uint32_t)(t << 7) | (uint32_t)col;
#pragma unroll
                for (int mt = 0; mt < 2; ++mt) {
#pragma unroll
                    for (int half = 0; half < 2; ++half) {
                        float p = ysc * acc[mt][nt][half * 2 + j];
                        float d = fmaf(nsx[mt * 2 + half], p, y2c);
                        int ti = mt * 2 + half;
                        if (d < topv[ti][KNN - 1])
                            insert5(topv[ti],
                                __uint_as_float((__float_as_uint(d) & 0xFFFFF000u) | loc));
                    }
                }
            }
        }
        __syncthreads();
    }

    // ---- merge 8 lists per query through smem (values carry indices) ----
    float* mbuf = (float*)smem;
    const int lid = (wid & 1) * 4 + (lane & 3);
#pragma unroll
    for (int ti = 0; ti < 4; ++ti) {
        int mt = ti >> 1, half = ti & 1;
        int qloc = wq + mt * 16 + half * 8 + (lane >> 2);
        float* dst = mbuf + (qloc * 8 + lid) * KNN;
#pragma unroll
        for (int s = 0; s < KNN; ++s) dst[s] = topv[ti][s];
    }
    __syncthreads();
    if (tid < 128) {
        float best[KNN] = {FLT_MAX, FLT_MAX, FLT_MAX, FLT_MAX, FLT_MAX};
        const float* src = mbuf + tid * 8 * KNN;
#pragma unroll
        for (int c = 0; c < 8 * KNN; ++c) {
            float d = src[c];
            if (d < best[KNN - 1]) insert5(best, d);
        }
        float* dst = g_scr + (size_t)(q0 + tid) * NCAND + split * KNN;
#pragma unroll
        for (int s = 0; s < KNN; ++s) dst[s] = best[s];
    }
}

// ---------------------------------------------------------------------------
// phaseB: warp/query — coarse top-24 of 185, exact fp32 refine, top-5, output
// ---------------------------------------------------------------------------
__global__ void phaseB(const float* __restrict__ feat,
                       const float* __restrict__ bank,
                       const float* __restrict__ minv,
                       const float* __restrict__ maxv,
                       float* __restrict__ out) {
    const int lane = threadIdx.x & 31;
    const int q = blockIdx.x * (blockDim.x >> 5) + (threadIdx.x >> 5);
    if (q >= N_Q) return;

    const float INF = __int_as_float(0x7f800000);
    const float* src = g_scr + (size_t)q * NCAND;
    float v[6];
#pragma unroll
    for (int i = 0; i < 6; ++i) {
        int idx = i * 32 + lane;
        v[i] = (idx < NCAND) ? src[idx] : INF;
    }

    // coarse top-NREF: select + decode global row index
    int gidx[NREF];
#pragma unroll
    for (int p = 0; p < NREF; ++p) {
        float lm = v[0];
#pragma unroll
        for (int i = 1; i < 6; ++i) lm = fminf(lm, v[i]);
        float wmv = lm;
#pragma unroll
        for (int o = 16; o; o >>= 1) wmv = fminf(wmv, __shfl_xor_sync(0xFFFFFFFFu, wmv, o));
        unsigned mask = __ballot_sync(0xFFFFFFFFu, lm == wmv);
        int leader = __ffs(mask) - 1;
        int g = -1;
        if (lane == leader) {
            bool done = false;
#pragma unroll
            for (int i = 0; i < 6; ++i) {
                if (!done && v[i] == wmv) {
                    int cand = i * 32 + lane;
                    g = (cand / KNN) * RPS + (int)(__float_as_uint(wmv) & 0xFFFu);
                    v[i] = INF; done = true;
                }
            }
        }
        gidx[p] = __shfl_sync(0xFFFFFFFFu, g, leader);
    }

    // exact fp32 refinement
    float4 xv = *reinterpret_cast<const float4*>(feat + (size_t)q * 128 + lane * 4);
    float myd = INF;
#pragma unroll
    for (int p = 0; p < NREF; ++p) {
        float4 yv = *reinterpret_cast<const float4*>(bank + (size_t)gidx[p] * 128 + lane * 4);
        float dx = xv.x - yv.x, dy = xv.y - yv.y, dz = xv.z - yv.z, dw = xv.w - yv.w;
        float s = dx * dx + dy * dy + dz * dz + dw * dw;
#pragma unroll
        for (int o = 16; o; o >>= 1) s += __shfl_xor_sync(0xFFFFFFFFu, s, o);
        if (lane == p) myd = s;
    }

    // exact top-5 + normalize + mean
    float acc = 0.f;
#pragma unroll
    for (int p = 0; p < KNN; ++p) {
        float wmv = myd;
#pragma unroll
        for (int o = 16; o; o >>= 1) wmv = fminf(wmv, __shfl_xor_sync(0xFFFFFFFFu, wmv, o));
        acc += sqrtf(fmaxf(wmv, 0.f));
        unsigned mask = __ballot_sync(0xFFFFFFFFu, myd == wmv);
        if (lane == (__ffs(mask) - 1)) myd = INF;
    }

    if (lane == 0) {
        float mn = *minv, mx = *maxv;
        out[q] = (acc * (1.0f / (float)KNN) - mn) / (mx - mn);
    }
}

// ---------------------------------------------------------------------------
extern "C" void kernel_launch(void* const* d_in, const int* in_sizes, int n_in,
                              void* d_out, int out_size) {
    (void)in_sizes; (void)n_in; (void)out_size;
    const float* feat = (const float*)d_in[0];
    const float* bank = (const float*)d_in[1];
    const float* minv = (const float*)d_in[2];
    const float* maxv = (const float*)d_in[3];
    float* out = (float*)d_out;

    prep_bank<<<(M_PAD + 7) / 8, 256>>>(bank);
    prep_feat<<<(N_Q + 7) / 8, 256>>>(feat);

    cudaFuncSetAttribute(knn_main, cudaFuncAttributeMaxDynamicSharedMemorySize, SMEM_SZ);
    knn_main<<<dim3(SPLITS, QTILES), 256, SMEM_SZ>>>();

    phaseB<<<(N_Q * 32 + 255) / 256, 256>>>(feat, bank, minv, maxv, out);
}

// round 9
// speedup vs baseline: 1.2899x; 1.2899x over previous
#include <cuda_runtime.h>
#include <cuda_bf16.h>
#include <cfloat>
#include <cstdint>

#define N_Q    2048
#define M_B    100000
#define M_PAD  100224
#define KNN    5
#define SPLITS 37
#define RPS    2703            /* 37*2703 = 100011 >= 100000 */
#define BT     128
#define NT     22              /* ceil(2703/128) */
#define QTILES 16
#define NCAND  (SPLITS * KNN)  /* 185 */

// ---------------------------------------------------------------------------
// device scratch (bf16 hi only: 256 B per row)
// ---------------------------------------------------------------------------
__device__ __align__(256) __nv_bfloat16 g_bank1[(size_t)M_PAD * 128];
__device__ __align__(256) __nv_bfloat16 g_feat1[(size_t)N_Q * 128];
__device__ float g_y2p[M_PAD];
__device__ __align__(256) float g_y2t[(size_t)SPLITS * NT * 128];  // tile-aligned, INF-padded
__device__ float g_scratch[(size_t)N_Q * NCAND];

#define SWZ(o) ((o) ^ (((o) >> 3) & 0x70))

__device__ __forceinline__ uint32_t smem_u32(const void* p) {
    uint32_t a;
    asm("{ .reg .u64 t; cvta.to.shared.u64 t, %1; cvt.u32.u64 %0, t; }" : "=r"(a) : "l"(p));
    return a;
}

#define CP16(dst, src) asm volatile("cp.async.cg.shared.global [%0], [%1], 16;" :: "r"(dst), "l"(src))
#define CP_COMMIT()    asm volatile("cp.async.commit_group;" ::: "memory")
#define CP_WAIT1()     asm volatile("cp.async.wait_group 1;" ::: "memory")
#define CP_WAIT0()     asm volatile("cp.async.wait_group 0;" ::: "memory")

#define LDSM4(r0, r1, r2, r3, a)                                               \
    asm volatile("ldmatrix.sync.aligned.m8n8.x4.shared.b16 {%0,%1,%2,%3}, [%4];" \
        : "=r"(r0), "=r"(r1), "=r"(r2), "=r"(r3) : "r"(a))

__device__ __forceinline__ void mma16816(float* c,
    uint32_t a0, uint32_t a1, uint32_t a2, uint32_t a3, uint32_t b0, uint32_t b1) {
    asm("mma.sync.aligned.m16n8k16.row.col.f32.bf16.bf16.f32 "
        "{%0,%1,%2,%3}, {%4,%5,%6,%7}, {%8,%9}, {%0,%1,%2,%3};"
        : "+f"(c[0]), "+f"(c[1]), "+f"(c[2]), "+f"(c[3])
        : "r"(a0), "r"(a1), "r"(a2), "r"(a3), "r"(b0), "r"(b1));
}

__device__ __forceinline__ void insert5(float* t, float d) {
    t[4] = d;
#pragma unroll
    for (int s = 4; s > 0; --s) {
        float lo = fminf(t[s], t[s - 1]);
        float hi = fmaxf(t[s], t[s - 1]);
        t[s - 1] = lo; t[s] = hi;
    }
}

// ---------------------------------------------------------------------------
// prep: fp32 -> bf16 hi; bank also y2 (+INF padding); y2 tiled gather
// ---------------------------------------------------------------------------
__global__ void prep_bank(const float* __restrict__ bank) {
    int r = (blockIdx.x * blockDim.x + threadIdx.x) >> 5;
    int lane = threadIdx.x & 31;
    if (r >= M_PAD) return;
    float4 v = make_float4(0.f, 0.f, 0.f, 0.f);
    if (r < M_B) v = *reinterpret_cast<const float4*>(bank + (size_t)r * 128 + lane * 4);
    __nv_bfloat16 h[4] = {__float2bfloat16(v.x), __float2bfloat16(v.y),
                          __float2bfloat16(v.z), __float2bfloat16(v.w)};
    *reinterpret_cast<uint2*>(&g_bank1[(size_t)r * 128 + lane * 4]) = *reinterpret_cast<const uint2*>(h);
    float s = v.x * v.x + v.y * v.y + v.z * v.z + v.w * v.w;
#pragma unroll
    for (int o = 16; o; o >>= 1) s += __shfl_xor_sync(0xFFFFFFFFu, s, o);
    if (lane == 0) g_y2p[r] = (r < M_B) ? s : __int_as_float(0x7f800000);
}

__global__ void prep_feat(const float* __restrict__ feat) {
    int r = (blockIdx.x * blockDim.x + threadIdx.x) >> 5;
    int lane = threadIdx.x & 31;
    if (r >= N_Q) return;
    float4 v = *reinterpret_cast<const float4*>(feat + (size_t)r * 128 + lane * 4);
    __nv_bfloat16 h[4] = {__float2bfloat16(v.x), __float2bfloat16(v.y),
                          __float2bfloat16(v.z), __float2bfloat16(v.w)};
    *reinterpret_cast<uint2*>(&g_feat1[(size_t)r * 128 + lane * 4]) = *reinterpret_cast<const uint2*>(h);
}

// tile-aligned y2 with INF padding beyond each split's valid range
__global__ void prep_y2t() {
    int idx = blockIdx.x * blockDim.x + threadIdx.x;
    if (idx >= SPLITS * NT * 128) return;
    int s = idx / (NT * 128);
    int local = idx - s * (NT * 128);
    float v = __int_as_float(0x7f800000);
    if (local < RPS) v = g_y2p[s * RPS + local];   // already INF for rows >= M_B
    g_y2t[idx] = v;
}

// ---------------------------------------------------------------------------
// main: 128q x 128m x K128 bf16 HMMA + fused top-5, occ 2
// smem: A 32KB @0 (2 chunks x 16KB) | B 2x32KB @32768 | y2 2x512B @98304
// ---------------------------------------------------------------------------
#define SMEM_SZ 99328

__global__ void __launch_bounds__(256, 2)
knn_main() {
    extern __shared__ __align__(1024) char smem[];
    const uint32_t sb = smem_u32(smem);
    const int tid  = threadIdx.x;
    const int wid  = tid >> 5;
    const int lane = tid & 31;
    const int wq = (wid >> 1) * 32;     // 0,32,64,96
    const int wm = (wid & 1) * 64;      // 0,64

    const int split  = blockIdx.x;
    const int q0     = blockIdx.y * 128;
    const int rbegin = split * RPS;

    // ---- A tile: 128 rows x 256B, swizzled, loaded once ----
    {
        const char* ga = (const char*)g_feat1 + (size_t)q0 * 256;
#pragma unroll
        for (int it = 0; it < 8; ++it) {
            int seg = it * 256 + tid;
            int row = seg >> 4, by = (seg & 15) << 4;
            int ch = by >> 7, inb = by & 127;
            float4 v = *reinterpret_cast<const float4*>(ga + row * 256 + by);
            *reinterpret_cast<float4*>(smem + ch * 16384 + SWZ(row * 128 + inb)) = v;
        }
    }

    // ---- lane-invariant fragment addresses ----
    const int ka = (lane & 16) ? 16 : 0;
    uint32_t aBase[2]; int xa[2];
#pragma unroll
    for (int mt = 0; mt < 2; ++mt) {
        int mrow = wq + mt * 16 + (lane & 15);
        aBase[mt] = sb + mrow * 128;
        xa[mt] = (mrow & 7) * 16;
    }
    const int kb = ((lane >> 4) & 1) * 16;
    const int nr = ((lane >> 3) & 1) * 8 + (lane & 7);
    uint32_t bRel[4]; int xb[4];
#pragma unroll
    for (int g = 0; g < 4; ++g) {
        int nrow = wm + g * 16 + nr;
        bRel[g] = nrow * 128;
        xb[g] = (nrow & 7) * 16;
    }

    // ---- B + y2 stage, fully async (y2 from tile-aligned g_y2t) ----
    auto stageB = [&](int st, int t) {
        const char* gb = (const char*)g_bank1 + (size_t)(rbegin + t * BT) * 256;
        uint32_t bs = sb + 32768 + st * 32768;
#pragma unroll
        for (int it = 0; it < 8; ++it) {
            int seg = it * 256 + tid;
            int row = seg >> 4, by = (seg & 15) << 4;
            int ch = by >> 7, inb = by & 127;
            CP16(bs + ch * 16384 + SWZ(row * 128 + inb), gb + row * 256 + by);
        }
        if (tid < 32)
            CP16(sb + 98304 + st * 512 + tid * 16,
                 (const char*)g_y2t + ((size_t)(split * NT + t) * 512) + tid * 16);
        CP_COMMIT();
    };

    stageB(0, 0);

    float top[4][KNN];
#pragma unroll
    for (int i = 0; i < 4; ++i)
#pragma unroll
        for (int s = 0; s < KNN; ++s) top[i][s] = FLT_MAX;

    for (int t = 0; t < NT; ++t) {
        const int st = t & 1;
        if (t + 1 < NT) { stageB(st ^ 1, t + 1); CP_WAIT1(); }
        else            { CP_WAIT0(); }
        __syncthreads();

        float acc[2][8][4];
#pragma unroll
        for (int mt = 0; mt < 2; ++mt)
#pragma unroll
            for (int nt = 0; nt < 8; ++nt)
#pragma unroll
                for (int c = 0; c < 4; ++c) acc[mt][nt][c] = 0.f;

        const uint32_t bs = sb + 32768 + st * 32768;
#pragma unroll
        for (int ks = 0; ks < 8; ++ks) {
            const uint32_t ca = (ks >> 2) * 16384u;
            const int kk = (ks & 3) * 32;
            uint32_t A[2][4], B[4][4];
            LDSM4(A[0][0], A[0][1], A[0][2], A[0][3], aBase[0] + ca + ((kk + ka) ^ xa[0]));
            LDSM4(A[1][0], A[1][1], A[1][2], A[1][3], aBase[1] + ca + ((kk + ka) ^ xa[1]));
#pragma unroll
            for (int g = 0; g < 4; ++g)
                LDSM4(B[g][0], B[g][1], B[g][2], B[g][3],
                      bs + ca + bRel[g] + ((kk + kb) ^ xb[g]));
#pragma unroll
            for (int mt = 0; mt < 2; ++mt)
#pragma unroll
                for (int nt = 0; nt < 8; ++nt)
                    mma16816(acc[mt][nt], A[mt][0], A[mt][1], A[mt][2], A[mt][3],
                             B[nt >> 1][nt & 1], B[nt >> 1][(nt & 1) + 2]);
        }

        // ---- fused epilogue (INF padding baked into y2 -> no bounds check) ----
        const float* y2s = (const float*)(smem + 98304 + st * 512);
#pragma unroll
        for (int nt = 0; nt < 8; ++nt) {
#pragma unroll
            for (int j = 0; j < 2; ++j) {
                float yv = y2s[wm + nt * 8 + (lane & 3) * 2 + j];
#pragma unroll
                for (int mt = 0; mt < 2; ++mt) {
#pragma unroll
                    for (int half = 0; half < 2; ++half) {
                        float d = fmaf(-2.0f, acc[mt][nt][half * 2 + j], yv);
                        int ti = mt * 2 + half;
                        if (d < top[ti][KNN - 1]) insert5(top[ti], d);
                    }
                }
            }
        }
        __syncthreads();
    }

    // ---- merge 8 lists per query through smem (reuse B region) ----
    float* mbuf = (float*)(smem + 32768);
    const int lid = (wid & 1) * 4 + (lane & 3);
#pragma unroll
    for (int ti = 0; ti < 4; ++ti) {
        int mt = ti >> 1, half = ti & 1;
        int qloc = wq + mt * 16 + half * 8 + (lane >> 2);
        float* dst = mbuf + (qloc * 8 + lid) * KNN;
#pragma unroll
        for (int s = 0; s < KNN; ++s) dst[s] = top[ti][s];
    }
    __syncthreads();
    if (tid < 128) {
        float best[KNN] = {FLT_MAX, FLT_MAX, FLT_MAX, FLT_MAX, FLT_MAX};
        const float* src = mbuf + tid * 8 * KNN;
#pragma unroll
        for (int c = 0; c < 8 * KNN; ++c) {
            float d = src[c];
            if (d < best[KNN - 1]) insert5(best, d);
        }
        float* dst = g_scratch + ((size_t)(q0 + tid) * SPLITS + split) * KNN;
#pragma unroll
        for (int s = 0; s < KNN; ++s) dst[s] = best[s];
    }
}

// ---------------------------------------------------------------------------
// phaseB: one warp per query — 5-pass warp-min select over 185 candidates
// ---------------------------------------------------------------------------
__global__ void phaseB(const float* __restrict__ feat,
                       const float* __restrict__ minv,
                       const float* __restrict__ maxv,
                       float* __restrict__ out) {
    const int lane = threadIdx.x & 31;
    const int q = blockIdx.x * (blockDim.x >> 5) + (threadIdx.x >> 5);
    if (q >= N_Q) return;

    const float INF = __int_as_float(0x7f800000);
    const float* src = g_scratch + (size_t)q * NCAND;
    float v[6];
#pragma unroll
    for (int i = 0; i < 6; ++i) {
        int idx = i * 32 + lane;
        v[i] = (idx < NCAND) ? src[idx] : INF;
    }

    // x2 warp-reduced
    float4 fv = *reinterpret_cast<const float4*>(feat + (size_t)q * 128 + lane * 4);
    float x2 = fv.x * fv.x + fv.y * fv.y + fv.z * fv.z + fv.w * fv.w;
#pragma unroll
    for (int o = 16; o; o >>= 1) x2 += __shfl_xor_sync(0xFFFFFFFFu, x2, o);

    float best[KNN];
#pragma unroll
    for (int p = 0; p < KNN; ++p) {
        float lm = v[0];
#pragma unroll
        for (int i = 1; i < 6; ++i) lm = fminf(lm, v[i]);
        float wm = lm;
#pragma unroll
        for (int o = 16; o; o >>= 1) wm = fminf(wm, __shfl_xor_sync(0xFFFFFFFFu, wm, o));
        unsigned mask = __ballot_sync(0xFFFFFFFFu, lm == wm);
        int leader = __ffs(mask) - 1;
        if (lane == leader) {
            bool done = false;
#pragma unroll
            for (int i = 0; i < 6; ++i)
                if (!done && v[i] == wm) { v[i] = INF; done = true; }
        }
        best[p] = wm;
    }

    if (lane == 0) {
        float mn = *minv, mx = *maxv;
        float inv = 1.0f / (mx - mn);
        float acc = 0.f;
#pragma unroll
        for (int s = 0; s < KNN; ++s) {
            float d2 = fmaxf(x2 + best[s], 0.f);
            acc += (sqrtf(d2) - mn) * inv;
        }
        out[q] = acc * (1.0f / (float)KNN);
    }
}

// ---------------------------------------------------------------------------
extern "C" void kernel_launch(void* const* d_in, const int* in_sizes, int n_in,
                              void* d_out, int out_size) {
    (void)in_sizes; (void)n_in; (void)out_size;
    const float* feat = (const float*)d_in[0];
    const float* bank = (const float*)d_in[1];
    const float* minv = (const float*)d_in[2];
    const float* maxv = (const float*)d_in[3];
    float* out = (float*)d_out;

    prep_bank<<<(M_PAD + 7) / 8, 256>>>(bank);
    prep_feat<<<(N_Q + 7) / 8, 256>>>(feat);
    prep_y2t<<<(SPLITS * NT * 128 + 255) / 256, 256>>>();

    cudaFuncSetAttribute(knn_main, cudaFuncAttributeMaxDynamicSharedMemorySize, SMEM_SZ);
    knn_main<<<dim3(SPLITS, QTILES), 256, SMEM_SZ>>>();

    phaseB<<<(N_Q * 32 + 255) / 256, 256>>>(feat, minv, maxv, out);
}